// round 10
// baseline (speedup 1.0000x reference)
#include <cuda_runtime.h>
#include <cuda_fp16.h>
#include <math.h>
#include <cstdint>

// ---------------- problem constants ----------------
#define T_TOK   2048
#define DM      4096
#define NH      32
#define KVH     8
#define HD      128
#define QKV_N   6144
#define K_OFF   4096
#define V_OFF   5120
#define CLIPV   8.0f
#define SCALE   0.08838834764831845f
#define KTOT    4096

// ---------------- scratch ----------------
__device__ float g_qkv[T_TOK * QKV_N];
__device__ __align__(16) __half g_ah  [T_TOK * DM];
__device__ __align__(16) __half g_bhi [QKV_N * DM];
__device__ __align__(16) __half g_blo [QKV_N * DM];
__device__ __align__(16) __half g_bohi[DM * DM];
__device__ __align__(16) __half g_bolo[DM * DM];
__device__ __align__(16) __half g_qhi[T_TOK * DM];
__device__ __align__(16) __half g_qlo[T_TOK * DM];
__device__ __align__(16) __half g_khi[T_TOK * KVH * HD];
__device__ __align__(16) __half g_klo[T_TOK * KVH * HD];
__device__ __align__(16) __half g_vthi[KVH * HD * T_TOK];
__device__ __align__(16) __half g_vtlo[KVH * HD * T_TOK];

// ============================ PTX helpers ============================
__device__ __forceinline__ uint32_t smem_u32_of(const void* p) {
    uint32_t a;
    asm("{ .reg .u64 t; cvta.to.shared.u64 t, %1; cvt.u32.u64 %0, t; }"
        : "=r"(a) : "l"(p));
    return a;
}
__device__ __forceinline__ void cp_async16(uint32_t dst, const void* src) {
    asm volatile("cp.async.cg.shared.global [%0], [%1], 16;" :: "r"(dst), "l"(src));
}
__device__ __forceinline__ void cp_commit() {
    asm volatile("cp.async.commit_group;" ::: "memory");
}
template<int N> __device__ __forceinline__ void cp_wait() {
    asm volatile("cp.async.wait_group %0;" :: "n"(N) : "memory");
}
__device__ __forceinline__ void ldsm4(uint32_t (&r)[4], uint32_t addr) {
    asm volatile("ldmatrix.sync.aligned.m8n8.x4.shared.b16 {%0,%1,%2,%3}, [%4];"
        : "=r"(r[0]), "=r"(r[1]), "=r"(r[2]), "=r"(r[3]) : "r"(addr));
}
__device__ __forceinline__ void mma16816(float (&d)[4], const uint32_t (&a)[4],
                                         const uint32_t* b) {
    asm volatile("mma.sync.aligned.m16n8k16.row.col.f32.f16.f16.f32 "
        "{%0,%1,%2,%3}, {%4,%5,%6,%7}, {%8,%9}, {%0,%1,%2,%3};"
        : "+f"(d[0]), "+f"(d[1]), "+f"(d[2]), "+f"(d[3])
        : "r"(a[0]), "r"(a[1]), "r"(a[2]), "r"(a[3]), "r"(b[0]), "r"(b[1]));
}
__device__ __forceinline__ uint32_t swoff(int row, int cch) {
    return (uint32_t)(row * 128 + (((cch) ^ (row & 7)) << 4));
}

// ============================================================================
// convert fp32 -> fp16 (8 elems/thread)
// ============================================================================
__global__ void __launch_bounds__(256) cvt_half_kernel(
    const float* __restrict__ in, __half* __restrict__ out, int n8)
{
    int i = blockIdx.x * 256 + threadIdx.x;
    if (i >= n8) return;
    float4 v0 = ((const float4*)in)[2 * i];
    float4 v1 = ((const float4*)in)[2 * i + 1];
    float a[8] = {v0.x, v0.y, v0.z, v0.w, v1.x, v1.y, v1.z, v1.w};
    __half h[8];
#pragma unroll
    for (int j = 0; j < 8; j++) h[j] = __float2half(a[j]);
    ((uint4*)out)[i] = *(uint4*)h;
}

// ============================================================================
// split fp32 -> fp16 hi/lo (8 elems/thread)
// ============================================================================
__global__ void __launch_bounds__(256) split_kernel(
    const float* __restrict__ in, __half* __restrict__ hi,
    __half* __restrict__ lo, int n8)
{
    int i = blockIdx.x * 256 + threadIdx.x;
    if (i >= n8) return;
    float4 v0 = ((const float4*)in)[2 * i];
    float4 v1 = ((const float4*)in)[2 * i + 1];
    float a[8] = {v0.x, v0.y, v0.z, v0.w, v1.x, v1.y, v1.z, v1.w};
    __half h[8], l[8];
#pragma unroll
    for (int j = 0; j < 8; j++) {
        h[j] = __float2half(a[j]);
        l[j] = __float2half(a[j] - __half2float(h[j]));
    }
    ((uint4*)hi)[i] = *(uint4*)h;
    ((uint4*)lo)[i] = *(uint4*)l;
}

// ============================================================================
// HMMA GEMM: C[M,N] = A[M,K] * B[N,K]^T, fp16 2-pass.
// CTA 128x256, BK=64, 16 warps (2x8), warp tile 64x32.
// Stage: A 16KB | Bhi 32KB | Blo 32KB = 80KB; 2 stages = 160KB, occ 1.
// ============================================================================
#define STAGE_BYTES 81920
#define GEMM_SMEM   (2 * STAGE_BYTES)
#define NCHUNK      (KTOT / 64)

__global__ void __launch_bounds__(512, 1) gemm_tc_kernel(
    const __half* __restrict__ Ah, const __half* __restrict__ Bhi,
    const __half* __restrict__ Blo,
    float* __restrict__ C, int Ntot, int doClip)
{
    extern __shared__ char smem[];
    const uint32_t sb = smem_u32_of(smem);
    const int tid  = threadIdx.x;
    const int wid  = tid >> 5;
    const int lane = tid & 31;
    const int warp_m = wid >> 3;      // 0..1
    const int warp_n = wid & 7;       // 0..7
    const int m0 = blockIdx.y * 128;
    const int n0 = blockIdx.x * 256;

    const int g = lane >> 3, r = lane & 7;
    const int a_row  = warp_m * 64 + (g & 1) * 8 + r;
    const int a_csel = g >> 1;
    const int b_row  = warp_n * 32 + (g >> 1) * 8 + r;
    const int b_csel = g & 1;

    float acc[4][4][4];
#pragma unroll
    for (int i = 0; i < 4; i++)
#pragma unroll
        for (int j = 0; j < 4; j++)
#pragma unroll
            for (int k = 0; k < 4; k++) acc[i][j][k] = 0.0f;

#define LOAD_CHUNK(cc, ss) do { \
    const int k0_ = (cc) * 64; \
    const uint32_t sbase_ = sb + (ss) * STAGE_BYTES; \
    _Pragma("unroll") \
    for (int t_ = 0; t_ < 2; t_++) { \
        int w_ = tid + t_ * 512; \
        int row_ = w_ >> 3, c_ = w_ & 7; \
        cp_async16(sbase_ + swoff(row_, c_), \
                   Ah + (size_t)(m0 + row_) * KTOT + k0_ + c_ * 8); \
    } \
    _Pragma("unroll") \
    for (int t_ = 0; t_ < 4; t_++) { \
        int w_ = tid + t_ * 512; \
        int row_ = w_ >> 3, c_ = w_ & 7; \
        cp_async16(sbase_ + 16384 + swoff(row_, c_), \
                   Bhi + (size_t)(n0 + row_) * KTOT + k0_ + c_ * 8); \
    } \
    _Pragma("unroll") \
    for (int t_ = 0; t_ < 4; t_++) { \
        int w_ = tid + t_ * 512; \
        int row_ = w_ >> 3, c_ = w_ & 7; \
        cp_async16(sbase_ + 49152 + swoff(row_, c_), \
                   Blo + (size_t)(n0 + row_) * KTOT + k0_ + c_ * 8); \
    } \
    cp_commit(); \
} while (0)

    LOAD_CHUNK(0, 0);

    for (int c = 0; c < NCHUNK; c++) {
        __syncthreads();
        if (c + 1 < NCHUNK) {
            LOAD_CHUNK(c + 1, (c + 1) & 1);
            cp_wait<1>();
        } else {
            cp_wait<0>();
        }
        __syncthreads();

        const uint32_t st = sb + (c & 1) * STAGE_BYTES;
#pragma unroll
        for (int s = 0; s < 4; s++) {
            uint32_t a_f[4][4];
#pragma unroll
            for (int mi = 0; mi < 4; mi++) {
                int m = a_row + mi * 16;
                uint32_t off = (uint32_t)(m * 128) +
                               ((((s << 1) + a_csel) ^ (m & 7)) << 4);
                ldsm4(a_f[mi], st + off);
            }
            uint32_t b_hi[2][4], b_lo[2][4];
#pragma unroll
            for (int j = 0; j < 2; j++) {
                int n = b_row + j * 16;
                uint32_t off = (uint32_t)(n * 128) +
                               ((((s << 1) + b_csel) ^ (n & 7)) << 4);
                ldsm4(b_hi[j], st + 16384 + off);
                ldsm4(b_lo[j], st + 49152 + off);
            }
#pragma unroll
            for (int mi = 0; mi < 4; mi++) {
#pragma unroll
                for (int nj = 0; nj < 4; nj++) {
                    const uint32_t* bh = &b_hi[nj >> 1][(nj & 1) * 2];
                    const uint32_t* bl = &b_lo[nj >> 1][(nj & 1) * 2];
                    mma16816(acc[mi][nj], a_f[mi], bh);
                    mma16816(acc[mi][nj], a_f[mi], bl);
                }
            }
        }
    }

    const int qrow = lane >> 2;
    const int qcol = (lane & 3) * 2;
#pragma unroll
    for (int mi = 0; mi < 4; mi++) {
#pragma unroll
        for (int nj = 0; nj < 4; nj++) {
            int m = m0 + warp_m * 64 + mi * 16 + qrow;
            int n = n0 + warp_n * 32 + nj * 8 + qcol;
            float v0 = acc[mi][nj][0], v1 = acc[mi][nj][1];
            float v2 = acc[mi][nj][2], v3 = acc[mi][nj][3];
            if (doClip) {
                v0 = fminf(CLIPV, fmaxf(-CLIPV, v0));
                v1 = fminf(CLIPV, fmaxf(-CLIPV, v1));
                v2 = fminf(CLIPV, fmaxf(-CLIPV, v2));
                v3 = fminf(CLIPV, fmaxf(-CLIPV, v3));
            }
            *(float2*)(C + (size_t)m * Ntot + n) = make_float2(v0, v1);
            *(float2*)(C + (size_t)(m + 8) * Ntot + n) = make_float2(v2, v3);
        }
    }
}

// ============================================================================
// RoPE: read fp32 g_qkv, write fp16 hi/lo Q and K
// ============================================================================
__global__ void __launch_bounds__(256) rope_kernel(
    const float* __restrict__ qkv, const float* __restrict__ cs,
    const float* __restrict__ sn,
    __half* __restrict__ Qhi, __half* __restrict__ Qlo,
    __half* __restrict__ Khi, __half* __restrict__ Klo)
{
    int t = blockIdx.x;
    int head = blockIdx.y * 4 + (threadIdx.x >> 6);
    int d = threadIdx.x & 63;
    float c = cs[t * 64 + d];
    float s = sn[t * 64 + d];
    size_t base;
    size_t obase;
    __half *hi, *lo;
    if (head < NH) {
        base = (size_t)t * QKV_N + head * HD;
        obase = (size_t)t * DM + head * HD;
        hi = Qhi; lo = Qlo;
    } else {
        base = (size_t)t * QKV_N + K_OFF + (head - NH) * HD;
        obase = (size_t)t * (KVH * HD) + (head - NH) * HD;
        hi = Khi; lo = Klo;
    }
    float x1 = qkv[base + d];
    float x2 = qkv[base + 64 + d];
    float y1 = x1 * c - x2 * s;
    float y2 = x2 * c + x1 * s;
    __half h1 = __float2half(y1);
    __half h2 = __float2half(y2);
    hi[obase + d]      = h1;
    hi[obase + 64 + d] = h2;
    lo[obase + d]      = __float2half(y1 - __half2float(h1));
    lo[obase + 64 + d] = __float2half(y2 - __half2float(h2));
}

// ============================================================================
// V transpose: g_qkv V section -> Vt[kvh][d][t] fp16 hi/lo
// ============================================================================
__global__ void __launch_bounds__(256) vtrans_kernel(
    const float* __restrict__ qkv,
    __half* __restrict__ Vthi, __half* __restrict__ Vtlo)
{
    __shared__ float vt[64][133];
    const int tid = threadIdx.x;
    const int tok0 = blockIdx.x * 64;
    const int kvh = blockIdx.y;

#pragma unroll
    for (int i = 0; i < 8; i++) {
        int idx = tid + i * 256;
        int row = idx >> 5;
        int c4  = (idx & 31) << 2;
        float4 v = *(const float4*)(qkv + (size_t)(tok0 + row) * QKV_N + V_OFF
                                    + kvh * HD + c4);
        vt[row][c4] = v.x; vt[row][c4 + 1] = v.y;
        vt[row][c4 + 2] = v.z; vt[row][c4 + 3] = v.w;
    }
    __syncthreads();

    if (tid < 128) {
        int d = tid;
        size_t obase = ((size_t)kvh * HD + d) * T_TOK + tok0;
#pragma unroll
        for (int gb = 0; gb < 8; gb++) {
            __half hb[8], lb[8];
#pragma unroll
            for (int u = 0; u < 8; u++) {
                float v = vt[gb * 8 + u][d];
                hb[u] = __float2half(v);
                lb[u] = __float2half(v - __half2float(hb[u]));
            }
            *(uint4*)(Vthi + obase + gb * 8) = *(uint4*)hb;
            *(uint4*)(Vtlo + obase + gb * 8) = *(uint4*)lb;
        }
    }
}

// ============================================================================
// Tensor-core flash attention with double-buffered K/V prefetch.
// ============================================================================
#define ATT_QHI 0
#define ATT_QLO 16384
#define ATT_KHI 32768        // + buf*16384  (bufs at 32768, 49152)
#define ATT_KLO 65536        // + buf*16384
#define ATT_VHI 98304        // + buf*16384
#define ATT_VLO 131072       // + buf*16384
#define ATT_PS  163840
#define ATT_SS  172032
#define ATT_ALPHA (ATT_SS + 17408)
#define ATT_LROW  (ATT_ALPHA + 256)
#define ATT_SMEM  (ATT_LROW + 256)

__global__ void __launch_bounds__(256) attn_kernel(
    const __half* __restrict__ Qhi, const __half* __restrict__ Qlo,
    const __half* __restrict__ Khi, const __half* __restrict__ Klo,
    const __half* __restrict__ Vthi, const __half* __restrict__ Vtlo,
    __half* __restrict__ oh)
{
    extern __shared__ char smc[];
    const uint32_t sbm = smem_u32_of(smc);
    float* Ss     = (float*)(smc + ATT_SS);
    float* alphas = (float*)(smc + ATT_ALPHA);
    float* lrow   = (float*)(smc + ATT_LROW);

    const int tid = threadIdx.x;
    const int h   = blockIdx.y;
    const int qb  = blockIdx.x;

    int seq, qb_local;
    if      (qb < 8)  { seq = 0; qb_local = qb; }
    else if (qb < 20) { seq = 1; qb_local = qb - 8; }
    else if (qb < 26) { seq = 2; qb_local = qb - 20; }
    else              { seq = 3; qb_local = qb - 26; }
    const int cu[4] = {0, 512, 1280, 1664};
    const int seq_start = cu[seq];
    const int q_start = seq_start + qb_local * 64;
    const int kh = h >> 2;

    const int wid = tid >> 5, lane = tid & 31;
    const int warp_m = wid & 3;
    const int warp_n = wid >> 2;
    const int g = lane >> 3, r = lane & 7;
    const int a_row  = warp_m * 16 + (g & 1) * 8 + r;
    const int a_csel = g >> 1;
    const int b_row  = warp_n * 32 + (g >> 1) * 8 + r;
    const int b_csel = g & 1;
    const int pb_row = (g >> 1) * 8 + r;
    const int qrow = lane >> 2, qcol = (lane & 3) * 2;
    const int srow = tid >> 2, sq = tid & 3;

#define LOAD_KV(tok0_, bb_) do { \
    _Pragma("unroll") \
    for (int t = 0; t < 8; t++) { \
        int id = tid + t * 256; \
        int buf = id >> 10; \
        int w = id & 1023; \
        int half_ = w >> 9; \
        int w2 = w & 511; \
        int trow = w2 >> 3, cch = w2 & 7; \
        const __half* src = (buf ? Klo : Khi) + \
            (size_t)((tok0_) + trow) * (KVH * HD) + kh * HD + half_ * 64 + cch * 8; \
        uint32_t dst = sbm + (buf ? ATT_KLO : ATT_KHI) + (bb_) * 16384 + \
                       half_ * 8192 + swoff(trow, cch); \
        cp_async16(dst, src); \
    } \
    _Pragma("unroll") \
    for (int t = 0; t < 8; t++) { \
        int id = tid + t * 256; \
        int buf = id >> 10; \
        int w = id & 1023; \
        int drow = w >> 3, cch = w & 7; \
        int half_ = drow >> 6, rl = drow & 63; \
        const __half* src = (buf ? Vtlo : Vthi) + \
            ((size_t)kh * HD + drow) * T_TOK + (tok0_) + cch * 8; \
        uint32_t dst = sbm + (buf ? ATT_VLO : ATT_VHI) + (bb_) * 16384 + \
                       half_ * 8192 + swoff(rl, cch); \
        cp_async16(dst, src); \
    } \
} while (0)

    // ---- preload Q + first K/V (one group) ----
#pragma unroll
    for (int t = 0; t < 8; t++) {
        int id = tid + t * 256;
        int buf = id >> 10;
        int w = id & 1023;
        int half_ = w >> 9;
        int w2 = w & 511;
        int trow = w2 >> 3, cch = w2 & 7;
        const __half* src = (buf ? Qlo : Qhi) +
            (size_t)(q_start + trow) * DM + h * HD + half_ * 64 + cch * 8;
        uint32_t dst = sbm + (buf ? ATT_QLO : ATT_QHI) + half_ * 8192 + swoff(trow, cch);
        cp_async16(dst, src);
    }
    LOAD_KV(seq_start, 0);
    cp_commit();

    float m_run = -INFINITY, l_run = 0.0f;
    float o[8][4];
#pragma unroll
    for (int i = 0; i < 8; i++)
#pragma unroll
        for (int j = 0; j < 4; j++) o[i][j] = 0.0f;

    for (int kb = 0; kb <= qb_local; kb++) {
        const int cur = kb & 1;
        cp_wait<0>();
        __syncthreads();

        // ---- QK^T (3-pass) from K[cur] ----
        float sacc[4][4];
#pragma unroll
        for (int i = 0; i < 4; i++)
#pragma unroll
            for (int j = 0; j < 4; j++) sacc[i][j] = 0.0f;

#pragma unroll
        for (int half_ = 0; half_ < 2; half_++) {
#pragma unroll
            for (int s4 = 0; s4 < 4; s4++) {
                uint32_t offa = half_ * 8192 + swoff(a_row, (s4 << 1) + a_csel);
                uint32_t ah4[4], al4[4];
                ldsm4(ah4, sbm + ATT_QHI + offa);
                ldsm4(al4, sbm + ATT_QLO + offa);
                uint32_t bh[2][4], bl[2][4];
#pragma unroll
                for (int jb = 0; jb < 2; jb++) {
                    uint32_t offb = cur * 16384 + half_ * 8192 +
                                    swoff(b_row + jb * 16, (s4 << 1) + b_csel);
                    ldsm4(bh[jb], sbm + ATT_KHI + offb);
                    ldsm4(bl[jb], sbm + ATT_KLO + offb);
                }
#pragma unroll
                for (int nj = 0; nj < 4; nj++) {
                    const uint32_t* ph = &bh[nj >> 1][(nj & 1) * 2];
                    const uint32_t* pl = &bl[nj >> 1][(nj & 1) * 2];
                    mma16816(sacc[nj], ah4, ph);
                    mma16816(sacc[nj], ah4, pl);
                    mma16816(sacc[nj], al4, ph);
                }
            }
        }

        // ---- prefetch next K/V into alternate buffers ----
        if (kb < qb_local) {
            LOAD_KV(seq_start + (kb + 1) * 64, cur ^ 1);
            cp_commit();
        }

        // ---- write S with scale + causal mask ----
        const bool diag = (kb == qb_local);
#pragma unroll
        for (int nj = 0; nj < 4; nj++) {
            int mloc = warp_m * 16 + qrow;
            int cloc = warp_n * 32 + nj * 8 + qcol;
            float v0 = sacc[nj][0] * SCALE;
            float v1 = sacc[nj][1] * SCALE;
            float v2 = sacc[nj][2] * SCALE;
            float v3 = sacc[nj][3] * SCALE;
            if (diag) {
                if (cloc     > mloc)     v0 = -1e30f;
                if (cloc + 1 > mloc)     v1 = -1e30f;
                if (cloc     > mloc + 8) v2 = -1e30f;
                if (cloc + 1 > mloc + 8) v3 = -1e30f;
            }
            Ss[mloc * 68 + cloc]           = v0;
            Ss[mloc * 68 + cloc + 1]       = v1;
            Ss[(mloc + 8) * 68 + cloc]     = v2;
            Ss[(mloc + 8) * 68 + cloc + 1] = v3;
        }
        __syncthreads();

        // ---- online softmax, P -> fp16 swizzled ----
        {
            float lmax = -INFINITY;
            int base = srow * 68 + sq * 16;
#pragma unroll
            for (int jj = 0; jj < 16; jj++)
                lmax = fmaxf(lmax, Ss[base + jj]);
            lmax = fmaxf(lmax, __shfl_xor_sync(0xffffffffu, lmax, 1));
            lmax = fmaxf(lmax, __shfl_xor_sync(0xffffffffu, lmax, 2));
            float m_new = fmaxf(m_run, lmax);
            float alpha = __expf(m_run - m_new);
            float lsum = 0.0f;
#pragma unroll
            for (int jj = 0; jj < 16; jj += 2) {
                float p0 = __expf(Ss[base + jj] - m_new);
                float p1 = __expf(Ss[base + jj + 1] - m_new);
                lsum += p0 + p1;
                int col = sq * 16 + jj;
                uint32_t byte = (uint32_t)(srow * 128) +
                    ((((col >> 3)) ^ (srow & 7)) << 4) + (col & 7) * 2;
                *(__half2*)(smc + ATT_PS + byte) = __floats2half2_rn(p0, p1);
            }
            lsum += __shfl_xor_sync(0xffffffffu, lsum, 1);
            lsum += __shfl_xor_sync(0xffffffffu, lsum, 2);
            l_run = l_run * alpha + lsum;
            m_run = m_new;
            if ((tid & 3) == 0) { alphas[srow] = alpha; lrow[srow] = l_run; }
        }
        __syncthreads();

        // ---- PV: o = o*alpha + P @ V[cur] (2-pass on V) ----
        {
            float a0 = alphas[warp_m * 16 + qrow];
            float a1 = alphas[warp_m * 16 + qrow + 8];
#pragma unroll
            for (int nj = 0; nj < 8; nj++) {
                o[nj][0] *= a0; o[nj][1] *= a0;
                o[nj][2] *= a1; o[nj][3] *= a1;
            }
#pragma unroll
            for (int s4 = 0; s4 < 4; s4++) {
                uint32_t ap[4];
                ldsm4(ap, sbm + ATT_PS + swoff(a_row, (s4 << 1) + a_csel));
                uint32_t vh[4][4], vl[4][4];
#pragma unroll
                for (int nb = 0; nb < 4; nb++) {
                    uint32_t offv = cur * 16384 + warp_n * 8192 +
                        swoff(pb_row + nb * 16, (s4 << 1) + b_csel);
                    ldsm4(vh[nb], sbm + ATT_VHI + offv);
                    ldsm4(vl[nb], sbm + ATT_VLO + offv);
                }
#pragma unroll
                for (int nj = 0; nj < 8; nj++) {
                    const uint32_t* ph = &vh[nj >> 1][(nj & 1) * 2];
                    const uint32_t* pl = &vl[nj >> 1][(nj & 1) * 2];
                    mma16816(o[nj], ap, ph);
                    mma16816(o[nj], ap, pl);
                }
            }
        }
        // no trailing sync: next-iter top sync protects SS/PS/alphas reuse
    }

    float inv0 = 1.0f / lrow[warp_m * 16 + qrow];
    float inv1 = 1.0f / lrow[warp_m * 16 + qrow + 8];
#pragma unroll
    for (int nj = 0; nj < 8; nj++) {
        int m = q_start + warp_m * 16 + qrow;
        int col = h * HD + warp_n * 64 + nj * 8 + qcol;
        *(__half2*)(oh + (size_t)m * DM + col) =
            __floats2half2_rn(o[nj][0] * inv0, o[nj][1] * inv0);
        *(__half2*)(oh + (size_t)(m + 8) * DM + col) =
            __floats2half2_rn(o[nj][2] * inv1, o[nj][3] * inv1);
    }
}

// ============================================================================
// launch — multi-stream fork/join (graph-capture safe)
// ============================================================================
extern "C" void kernel_launch(void* const* d_in, const int* in_sizes, int n_in,
                              void* d_out, int out_size)
{
    const float* hs    = (const float*)d_in[0];
    const float* w_qkv = (const float*)d_in[1];
    const float* w_o   = (const float*)d_in[2];
    const float* cs    = (const float*)d_in[3];
    const float* sn    = (const float*)d_in[4];
    (void)in_sizes; (void)n_in;

    float* qkv_buf = nullptr;
    __half *ah, *bhi, *blo, *bohi, *bolo, *qhi, *qlo, *khi, *klo, *vthi, *vtlo;
    cudaGetSymbolAddress((void**)&qkv_buf, g_qkv);
    cudaGetSymbolAddress((void**)&ah, g_ah);
    cudaGetSymbolAddress((void**)&bhi, g_bhi);
    cudaGetSymbolAddress((void**)&blo, g_blo);
    cudaGetSymbolAddress((void**)&bohi, g_bohi);
    cudaGetSymbolAddress((void**)&bolo, g_bolo);
    cudaGetSymbolAddress((void**)&qhi, g_qhi);
    cudaGetSymbolAddress((void**)&qlo, g_qlo);
    cudaGetSymbolAddress((void**)&khi, g_khi);
    cudaGetSymbolAddress((void**)&klo, g_klo);
    cudaGetSymbolAddress((void**)&vthi, g_vthi);
    cudaGetSymbolAddress((void**)&vtlo, g_vtlo);

    static cudaStream_t s1 = nullptr, s2 = nullptr;
    static cudaEvent_t eFork = nullptr, eWqkv = nullptr, eWo = nullptr,
                       eG1 = nullptr, eVt = nullptr;
    static int init_done = 0;
    if (!init_done) {
        cudaFuncSetAttribute(attn_kernel, cudaFuncAttributeMaxDynamicSharedMemorySize,
                             ATT_SMEM);
        cudaFuncSetAttribute(gemm_tc_kernel, cudaFuncAttributeMaxDynamicSharedMemorySize,
                             GEMM_SMEM);
        cudaStreamCreateWithFlags(&s1, cudaStreamNonBlocking);
        cudaStreamCreateWithFlags(&s2, cudaStreamNonBlocking);
        cudaEventCreateWithFlags(&eFork, cudaEventDisableTiming);
        cudaEventCreateWithFlags(&eWqkv, cudaEventDisableTiming);
        cudaEventCreateWithFlags(&eWo, cudaEventDisableTiming);
        cudaEventCreateWithFlags(&eG1, cudaEventDisableTiming);
        cudaEventCreateWithFlags(&eVt, cudaEventDisableTiming);
        init_done = 1;
    }

    cudaEventRecord(eFork, 0);
    cudaStreamWaitEvent(s1, eFork, 0);
    cudaStreamWaitEvent(s2, eFork, 0);

    split_kernel<<<(QKV_N * DM / 8) / 256, 256, 0, s1>>>(
        w_qkv, bhi, blo, QKV_N * DM / 8);
    cudaEventRecord(eWqkv, s1);

    split_kernel<<<(DM * DM / 8) / 256, 256, 0, s2>>>(
        w_o, bohi, bolo, DM * DM / 8);
    cudaEventRecord(eWo, s2);

    cvt_half_kernel<<<(T_TOK * DM / 8) / 256, 256>>>(hs, ah, T_TOK * DM / 8);
    cudaStreamWaitEvent(0, eWqkv, 0);
    gemm_tc_kernel<<<dim3(QKV_N / 256, T_TOK / 128), 512, GEMM_SMEM>>>(
        ah, bhi, blo, qkv_buf, QKV_N, 1);
    cudaEventRecord(eG1, 0);

    cudaStreamWaitEvent(s1, eG1, 0);
    vtrans_kernel<<<dim3(T_TOK / 64, KVH), 256, 0, s1>>>(qkv_buf, vthi, vtlo);
    cudaEventRecord(eVt, s1);

    rope_kernel<<<dim3(T_TOK, 10), 256>>>(qkv_buf, cs, sn, qhi, qlo, khi, klo);

    cudaStreamWaitEvent(0, eVt, 0);
    attn_kernel<<<dim3(32, NH), 256, ATT_SMEM>>>(qhi, qlo, khi, klo, vthi, vtlo, ah);

    cudaStreamWaitEvent(0, eWo, 0);
    gemm_tc_kernel<<<dim3(DM / 256, T_TOK / 128), 512, GEMM_SMEM>>>(
        ah, bohi, bolo, (float*)d_out, DM, 0);
}

// round 11
// speedup vs baseline: 1.5887x; 1.5887x over previous
#include <cuda_runtime.h>
#include <cuda_fp16.h>
#include <math.h>
#include <cstdint>

// ---------------- problem constants ----------------
#define T_TOK   2048
#define DM      4096
#define NH      32
#define KVH     8
#define HD      128
#define QKV_N   6144
#define CLIPV   8.0f
#define SCALE   0.08838834764831845f
#define KTOT    4096

// ---------------- scratch ----------------
__device__ __align__(16) __half g_ah  [T_TOK * DM];
__device__ __align__(16) __half g_bhi [QKV_N * DM];
__device__ __align__(16) __half g_blo [QKV_N * DM];
__device__ __align__(16) __half g_bohi[DM * DM];
__device__ __align__(16) __half g_bolo[DM * DM];
__device__ __align__(16) __half g_qhi[T_TOK * DM];
__device__ __align__(16) __half g_qlo[T_TOK * DM];
__device__ __align__(16) __half g_khi[T_TOK * KVH * HD];
__device__ __align__(16) __half g_klo[T_TOK * KVH * HD];
__device__ __align__(16) __half g_vthi[KVH * HD * T_TOK];
__device__ __align__(16) __half g_vtlo[KVH * HD * T_TOK];

// ============================ PTX helpers ============================
__device__ __forceinline__ uint32_t smem_u32_of(const void* p) {
    uint32_t a;
    asm("{ .reg .u64 t; cvta.to.shared.u64 t, %1; cvt.u32.u64 %0, t; }"
        : "=r"(a) : "l"(p));
    return a;
}
__device__ __forceinline__ void cp_async16(uint32_t dst, const void* src) {
    asm volatile("cp.async.cg.shared.global [%0], [%1], 16;" :: "r"(dst), "l"(src));
}
__device__ __forceinline__ void cp_commit() {
    asm volatile("cp.async.commit_group;" ::: "memory");
}
template<int N> __device__ __forceinline__ void cp_wait() {
    asm volatile("cp.async.wait_group %0;" :: "n"(N) : "memory");
}
__device__ __forceinline__ void ldsm4(uint32_t (&r)[4], uint32_t addr) {
    asm volatile("ldmatrix.sync.aligned.m8n8.x4.shared.b16 {%0,%1,%2,%3}, [%4];"
        : "=r"(r[0]), "=r"(r[1]), "=r"(r[2]), "=r"(r[3]) : "r"(addr));
}
__device__ __forceinline__ void mma16816(float (&d)[4], const uint32_t (&a)[4],
                                         const uint32_t* b) {
    asm volatile("mma.sync.aligned.m16n8k16.row.col.f32.f16.f16.f32 "
        "{%0,%1,%2,%3}, {%4,%5,%6,%7}, {%8,%9}, {%0,%1,%2,%3};"
        : "+f"(d[0]), "+f"(d[1]), "+f"(d[2]), "+f"(d[3])
        : "r"(a[0]), "r"(a[1]), "r"(a[2]), "r"(a[3]), "r"(b[0]), "r"(b[1]));
}
__device__ __forceinline__ uint32_t swoff(int row, int cch) {
    return (uint32_t)(row * 128 + (((cch) ^ (row & 7)) << 4));
}
__device__ __forceinline__ float clipf(float v) {
    return fminf(CLIPV, fmaxf(-CLIPV, v));
}

// ============================================================================
// convert fp32 -> fp16 (8 elems/thread)
// ============================================================================
__global__ void __launch_bounds__(256) cvt_half_kernel(
    const float* __restrict__ in, __half* __restrict__ out, int n8)
{
    int i = blockIdx.x * 256 + threadIdx.x;
    if (i >= n8) return;
    float4 v0 = ((const float4*)in)[2 * i];
    float4 v1 = ((const float4*)in)[2 * i + 1];
    float a[8] = {v0.x, v0.y, v0.z, v0.w, v1.x, v1.y, v1.z, v1.w};
    __half h[8];
#pragma unroll
    for (int j = 0; j < 8; j++) h[j] = __float2half(a[j]);
    ((uint4*)out)[i] = *(uint4*)h;
}

// ============================================================================
// split fp32 -> fp16 hi/lo (8 elems/thread)
// ============================================================================
__global__ void __launch_bounds__(256) split_kernel(
    const float* __restrict__ in, __half* __restrict__ hi,
    __half* __restrict__ lo, int n8)
{
    int i = blockIdx.x * 256 + threadIdx.x;
    if (i >= n8) return;
    float4 v0 = ((const float4*)in)[2 * i];
    float4 v1 = ((const float4*)in)[2 * i + 1];
    float a[8] = {v0.x, v0.y, v0.z, v0.w, v1.x, v1.y, v1.z, v1.w};
    __half h[8], l[8];
#pragma unroll
    for (int j = 0; j < 8; j++) {
        h[j] = __float2half(a[j]);
        l[j] = __float2half(a[j] - __half2float(h[j]));
    }
    ((uint4*)hi)[i] = *(uint4*)h;
    ((uint4*)lo)[i] = *(uint4*)l;
}

// ============================================================================
// HMMA GEMM (R8 proven core: 128x128, BK=64, 8 warps, 2x48KB stages, occ 2).
// FUSED=0: plain fp32 store to C.
// FUSED=1: QKV epilogue — clip, then per-head: RoPE+split (Q,K) or
//          transpose+split (V); writes fp16 hi/lo buffers directly.
// ============================================================================
#define STAGE_BYTES 49152
#define GEMM_SMEM   (2 * STAGE_BYTES)
#define NCHUNK      (KTOT / 64)

template<int FUSED>
__global__ void __launch_bounds__(256, 2) gemm_tc_kernel(
    const __half* __restrict__ Ah, const __half* __restrict__ Bhi,
    const __half* __restrict__ Blo,
    float* __restrict__ C, int Ntot,
    const float* __restrict__ cs_, const float* __restrict__ sn_,
    __half* __restrict__ Qhi, __half* __restrict__ Qlo,
    __half* __restrict__ Khi, __half* __restrict__ Klo,
    __half* __restrict__ Vthi, __half* __restrict__ Vtlo)
{
    extern __shared__ char smem[];
    const uint32_t sb = smem_u32_of(smem);
    const int tid  = threadIdx.x;
    const int wid  = tid >> 5;
    const int lane = tid & 31;
    const int warp_m = wid >> 2;
    const int warp_n = wid & 3;
    const int m0 = blockIdx.y * 128;
    const int n0 = blockIdx.x * 128;

    const __half* srcs[3];
    srcs[0] = Ah; srcs[1] = Bhi; srcs[2] = Blo;

    const int g = lane >> 3, r = lane & 7;
    const int a_row  = warp_m * 64 + (g & 1) * 8 + r;
    const int a_csel = g >> 1;
    const int b_row  = warp_n * 32 + (g >> 1) * 8 + r;
    const int b_csel = g & 1;

    float acc[4][4][4];
#pragma unroll
    for (int i = 0; i < 4; i++)
#pragma unroll
        for (int j = 0; j < 4; j++)
#pragma unroll
            for (int k = 0; k < 4; k++) acc[i][j][k] = 0.0f;

#define LOAD_CHUNK(cc, ss) do { \
    const int k0_ = (cc) * 64; \
    const uint32_t sbase_ = sb + (ss) * STAGE_BYTES; \
    _Pragma("unroll") \
    for (int t_ = 0; t_ < 12; t_++) { \
        int id_ = tid + t_ * 256; \
        int tile_ = id_ >> 10; \
        int w_ = id_ & 1023; \
        int mrow_ = w_ >> 3; \
        int cch_ = w_ & 7; \
        int grow_ = (tile_ == 0) ? (m0 + mrow_) : (n0 + mrow_); \
        const void* src_ = srcs[tile_] + (size_t)grow_ * KTOT + k0_ + cch_ * 8; \
        uint32_t dst_ = sbase_ + tile_ * 16384 + mrow_ * 128 + ((cch_ ^ (mrow_ & 7)) << 4); \
        cp_async16(dst_, src_); \
    } \
    cp_commit(); \
} while (0)

    LOAD_CHUNK(0, 0);

    for (int c = 0; c < NCHUNK; c++) {
        __syncthreads();
        if (c + 1 < NCHUNK) {
            LOAD_CHUNK(c + 1, (c + 1) & 1);
            cp_wait<1>();
        } else {
            cp_wait<0>();
        }
        __syncthreads();

        const uint32_t st = sb + (c & 1) * STAGE_BYTES;
#pragma unroll
        for (int s = 0; s < 4; s++) {
            uint32_t a_f[4][4];
#pragma unroll
            for (int mi = 0; mi < 4; mi++) {
                int m = a_row + mi * 16;
                uint32_t off = (uint32_t)(m * 128) +
                               ((((s << 1) + a_csel) ^ (m & 7)) << 4);
                ldsm4(a_f[mi], st + off);
            }
            uint32_t b_hi[2][4], b_lo[2][4];
#pragma unroll
            for (int j = 0; j < 2; j++) {
                int n = b_row + j * 16;
                uint32_t off = (uint32_t)(n * 128) +
                               ((((s << 1) + b_csel) ^ (n & 7)) << 4);
                ldsm4(b_hi[j], st + 16384 + off);
                ldsm4(b_lo[j], st + 32768 + off);
            }
#pragma unroll
            for (int mi = 0; mi < 4; mi++) {
#pragma unroll
                for (int nj = 0; nj < 4; nj++) {
                    const uint32_t* bh = &b_hi[nj >> 1][(nj & 1) * 2];
                    const uint32_t* bl = &b_lo[nj >> 1][(nj & 1) * 2];
                    mma16816(acc[mi][nj], a_f[mi], bh);
                    mma16816(acc[mi][nj], a_f[mi], bl);
                }
            }
        }
    }

    const int qrow = lane >> 2;
    const int qcol = (lane & 3) * 2;

    if (!FUSED) {
        // plain fp32 store
#pragma unroll
        for (int mi = 0; mi < 4; mi++) {
#pragma unroll
            for (int nj = 0; nj < 4; nj++) {
                int m = m0 + warp_m * 64 + mi * 16 + qrow;
                int n = n0 + warp_n * 32 + nj * 8 + qcol;
                *(float2*)(C + (size_t)m * Ntot + n) =
                    make_float2(acc[mi][nj][0], acc[mi][nj][1]);
                *(float2*)(C + (size_t)(m + 8) * Ntot + n) =
                    make_float2(acc[mi][nj][2], acc[mi][nj][3]);
            }
        }
        return;
    }

    // ---- FUSED epilogue: stage clipped tile in smem ----
    __syncthreads();   // all warps done with stage smem (ldsm of last chunk)
    float* Cs = (float*)smem;   // [128][132]
#pragma unroll
    for (int mi = 0; mi < 4; mi++) {
#pragma unroll
        for (int nj = 0; nj < 4; nj++) {
            int rr = warp_m * 64 + mi * 16 + qrow;
            int cc = warp_n * 32 + nj * 8 + qcol;
            Cs[rr * 132 + cc]           = clipf(acc[mi][nj][0]);
            Cs[rr * 132 + cc + 1]       = clipf(acc[mi][nj][1]);
            Cs[(rr + 8) * 132 + cc]     = clipf(acc[mi][nj][2]);
            Cs[(rr + 8) * 132 + cc + 1] = clipf(acc[mi][nj][3]);
        }
    }
    __syncthreads();

    const int head = n0 >> 7;          // 0..47
    if (head < NH + KVH) {
        // ---- RoPE + split for Q (head<32) or K ----
        __half *hi, *lo;
        size_t rowstride;
        int coff;
        if (head < NH) {
            hi = Qhi; lo = Qlo; rowstride = DM; coff = head * HD;
        } else {
            hi = Khi; lo = Klo; rowstride = KVH * HD; coff = (head - NH) * HD;
        }
        const int dp = (tid & 31) * 2;     // d pair base: 0..62
        const int r0 = tid >> 5;           // 0..7
#pragma unroll
        for (int it = 0; it < 16; it++) {
            int row = it * 8 + r0;
            int tok = m0 + row;
            float c0 = cs_[tok * 64 + dp],     c1 = cs_[tok * 64 + dp + 1];
            float s0 = sn_[tok * 64 + dp],     s1 = sn_[tok * 64 + dp + 1];
            float x10 = Cs[row * 132 + dp],      x11 = Cs[row * 132 + dp + 1];
            float x20 = Cs[row * 132 + dp + 64], x21 = Cs[row * 132 + dp + 65];
            float y10 = x10 * c0 - x20 * s0, y11 = x11 * c1 - x21 * s1;
            float y20 = x20 * c0 + x10 * s0, y21 = x21 * c1 + x11 * s1;
            __half h10 = __float2half(y10), h11 = __float2half(y11);
            __half h20 = __float2half(y20), h21 = __float2half(y21);
            __half l10 = __float2half(y10 - __half2float(h10));
            __half l11 = __float2half(y11 - __half2float(h11));
            __half l20 = __float2half(y20 - __half2float(h20));
            __half l21 = __float2half(y21 - __half2float(h21));
            size_t ob = (size_t)tok * rowstride + coff;
            *(__half2*)(hi + ob + dp)      = __halves2half2(h10, h11);
            *(__half2*)(hi + ob + dp + 64) = __halves2half2(h20, h21);
            *(__half2*)(lo + ob + dp)      = __halves2half2(l10, l11);
            *(__half2*)(lo + ob + dp + 64) = __halves2half2(l20, l21);
        }
    } else {
        // ---- V: transpose + split -> Vt[kvh][d][token] ----
        const int kvh = head - NH - KVH;
        const int d = tid & 127;
        const int hsel = tid >> 7;        // token half: 0 or 1
        size_t obase = ((size_t)kvh * HD + d) * T_TOK + m0 + hsel * 64;
#pragma unroll
        for (int gb = 0; gb < 8; gb++) {
            __half hb[8], lb[8];
#pragma unroll
            for (int u = 0; u < 8; u++) {
                float v = Cs[(hsel * 64 + gb * 8 + u) * 132 + d];
                hb[u] = __float2half(v);
                lb[u] = __float2half(v - __half2float(hb[u]));
            }
            *(uint4*)(Vthi + obase + gb * 8) = *(uint4*)hb;
            *(uint4*)(Vtlo + obase + gb * 8) = *(uint4*)lb;
        }
    }
}

// ============================================================================
// Tensor-core flash attention with double-buffered K/V prefetch (R10, proven
// correct; structure >= R7 perf).
// ============================================================================
#define ATT_QHI 0
#define ATT_QLO 16384
#define ATT_KHI 32768
#define ATT_KLO 65536
#define ATT_VHI 98304
#define ATT_VLO 131072
#define ATT_PS  163840
#define ATT_SS  172032
#define ATT_ALPHA (ATT_SS + 17408)
#define ATT_LROW  (ATT_ALPHA + 256)
#define ATT_SMEM  (ATT_LROW + 256)

__global__ void __launch_bounds__(256) attn_kernel(
    const __half* __restrict__ Qhi, const __half* __restrict__ Qlo,
    const __half* __restrict__ Khi, const __half* __restrict__ Klo,
    const __half* __restrict__ Vthi, const __half* __restrict__ Vtlo,
    __half* __restrict__ oh)
{
    extern __shared__ char smc[];
    const uint32_t sbm = smem_u32_of(smc);
    float* Ss     = (float*)(smc + ATT_SS);
    float* alphas = (float*)(smc + ATT_ALPHA);
    float* lrow   = (float*)(smc + ATT_LROW);

    const int tid = threadIdx.x;
    const int h   = blockIdx.y;
    const int qb  = blockIdx.x;

    int seq, qb_local;
    if      (qb < 8)  { seq = 0; qb_local = qb; }
    else if (qb < 20) { seq = 1; qb_local = qb - 8; }
    else if (qb < 26) { seq = 2; qb_local = qb - 20; }
    else              { seq = 3; qb_local = qb - 26; }
    const int cu[4] = {0, 512, 1280, 1664};
    const int seq_start = cu[seq];
    const int q_start = seq_start + qb_local * 64;
    const int kh = h >> 2;

    const int wid = tid >> 5, lane = tid & 31;
    const int warp_m = wid & 3;
    const int warp_n = wid >> 2;
    const int g = lane >> 3, r = lane & 7;
    const int a_row  = warp_m * 16 + (g & 1) * 8 + r;
    const int a_csel = g >> 1;
    const int b_row  = warp_n * 32 + (g >> 1) * 8 + r;
    const int b_csel = g & 1;
    const int pb_row = (g >> 1) * 8 + r;
    const int qrow = lane >> 2, qcol = (lane & 3) * 2;
    const int srow = tid >> 2, sq = tid & 3;

#define LOAD_KV(tok0_, bb_) do { \
    _Pragma("unroll") \
    for (int t = 0; t < 8; t++) { \
        int id = tid + t * 256; \
        int buf = id >> 10; \
        int w = id & 1023; \
        int half_ = w >> 9; \
        int w2 = w & 511; \
        int trow = w2 >> 3, cch = w2 & 7; \
        const __half* src = (buf ? Klo : Khi) + \
            (size_t)((tok0_) + trow) * (KVH * HD) + kh * HD + half_ * 64 + cch * 8; \
        uint32_t dst = sbm + (buf ? ATT_KLO : ATT_KHI) + (bb_) * 16384 + \
                       half_ * 8192 + swoff(trow, cch); \
        cp_async16(dst, src); \
    } \
    _Pragma("unroll") \
    for (int t = 0; t < 8; t++) { \
        int id = tid + t * 256; \
        int buf = id >> 10; \
        int w = id & 1023; \
        int drow = w >> 3, cch = w & 7; \
        int half_ = drow >> 6, rl = drow & 63; \
        const __half* src = (buf ? Vtlo : Vthi) + \
            ((size_t)kh * HD + drow) * T_TOK + (tok0_) + cch * 8; \
        uint32_t dst = sbm + (buf ? ATT_VLO : ATT_VHI) + (bb_) * 16384 + \
                       half_ * 8192 + swoff(rl, cch); \
        cp_async16(dst, src); \
    } \
} while (0)

#pragma unroll
    for (int t = 0; t < 8; t++) {
        int id = tid + t * 256;
        int buf = id >> 10;
        int w = id & 1023;
        int half_ = w >> 9;
        int w2 = w & 511;
        int trow = w2 >> 3, cch = w2 & 7;
        const __half* src = (buf ? Qlo : Qhi) +
            (size_t)(q_start + trow) * DM + h * HD + half_ * 64 + cch * 8;
        uint32_t dst = sbm + (buf ? ATT_QLO : ATT_QHI) + half_ * 8192 + swoff(trow, cch);
        cp_async16(dst, src);
    }
    LOAD_KV(seq_start, 0);
    cp_commit();

    float m_run = -INFINITY, l_run = 0.0f;
    float o[8][4];
#pragma unroll
    for (int i = 0; i < 8; i++)
#pragma unroll
        for (int j = 0; j < 4; j++) o[i][j] = 0.0f;

    for (int kb = 0; kb <= qb_local; kb++) {
        const int cur = kb & 1;
        cp_wait<0>();
        __syncthreads();

        float sacc[4][4];
#pragma unroll
        for (int i = 0; i < 4; i++)
#pragma unroll
            for (int j = 0; j < 4; j++) sacc[i][j] = 0.0f;

#pragma unroll
        for (int half_ = 0; half_ < 2; half_++) {
#pragma unroll
            for (int s4 = 0; s4 < 4; s4++) {
                uint32_t offa = half_ * 8192 + swoff(a_row, (s4 << 1) + a_csel);
                uint32_t ah4[4], al4[4];
                ldsm4(ah4, sbm + ATT_QHI + offa);
                ldsm4(al4, sbm + ATT_QLO + offa);
                uint32_t bh[2][4], bl[2][4];
#pragma unroll
                for (int jb = 0; jb < 2; jb++) {
                    uint32_t offb = cur * 16384 + half_ * 8192 +
                                    swoff(b_row + jb * 16, (s4 << 1) + b_csel);
                    ldsm4(bh[jb], sbm + ATT_KHI + offb);
                    ldsm4(bl[jb], sbm + ATT_KLO + offb);
                }
#pragma unroll
                for (int nj = 0; nj < 4; nj++) {
                    const uint32_t* ph = &bh[nj >> 1][(nj & 1) * 2];
                    const uint32_t* pl = &bl[nj >> 1][(nj & 1) * 2];
                    mma16816(sacc[nj], ah4, ph);
                    mma16816(sacc[nj], ah4, pl);
                    mma16816(sacc[nj], al4, ph);
                }
            }
        }

        if (kb < qb_local) {
            LOAD_KV(seq_start + (kb + 1) * 64, cur ^ 1);
            cp_commit();
        }

        const bool diag = (kb == qb_local);
#pragma unroll
        for (int nj = 0; nj < 4; nj++) {
            int mloc = warp_m * 16 + qrow;
            int cloc = warp_n * 32 + nj * 8 + qcol;
            float v0 = sacc[nj][0] * SCALE;
            float v1 = sacc[nj][1] * SCALE;
            float v2 = sacc[nj][2] * SCALE;
            float v3 = sacc[nj][3] * SCALE;
            if (diag) {
                if (cloc     > mloc)     v0 = -1e30f;
                if (cloc + 1 > mloc)     v1 = -1e30f;
                if (cloc     > mloc + 8) v2 = -1e30f;
                if (cloc + 1 > mloc + 8) v3 = -1e30f;
            }
            Ss[mloc * 68 + cloc]           = v0;
            Ss[mloc * 68 + cloc + 1]       = v1;
            Ss[(mloc + 8) * 68 + cloc]     = v2;
            Ss[(mloc + 8) * 68 + cloc + 1] = v3;
        }
        __syncthreads();

        {
            float lmax = -INFINITY;
            int base = srow * 68 + sq * 16;
#pragma unroll
            for (int jj = 0; jj < 16; jj++)
                lmax = fmaxf(lmax, Ss[base + jj]);
            lmax = fmaxf(lmax, __shfl_xor_sync(0xffffffffu, lmax, 1));
            lmax = fmaxf(lmax, __shfl_xor_sync(0xffffffffu, lmax, 2));
            float m_new = fmaxf(m_run, lmax);
            float alpha = __expf(m_run - m_new);
            float lsum = 0.0f;
#pragma unroll
            for (int jj = 0; jj < 16; jj += 2) {
                float p0 = __expf(Ss[base + jj] - m_new);
                float p1 = __expf(Ss[base + jj + 1] - m_new);
                lsum += p0 + p1;
                int col = sq * 16 + jj;
                uint32_t byte = (uint32_t)(srow * 128) +
                    ((((col >> 3)) ^ (srow & 7)) << 4) + (col & 7) * 2;
                *(__half2*)(smc + ATT_PS + byte) = __floats2half2_rn(p0, p1);
            }
            lsum += __shfl_xor_sync(0xffffffffu, lsum, 1);
            lsum += __shfl_xor_sync(0xffffffffu, lsum, 2);
            l_run = l_run * alpha + lsum;
            m_run = m_new;
            if ((tid & 3) == 0) { alphas[srow] = alpha; lrow[srow] = l_run; }
        }
        __syncthreads();

        {
            float a0 = alphas[warp_m * 16 + qrow];
            float a1 = alphas[warp_m * 16 + qrow + 8];
#pragma unroll
            for (int nj = 0; nj < 8; nj++) {
                o[nj][0] *= a0; o[nj][1] *= a0;
                o[nj][2] *= a1; o[nj][3] *= a1;
            }
#pragma unroll
            for (int s4 = 0; s4 < 4; s4++) {
                uint32_t ap[4];
                ldsm4(ap, sbm + ATT_PS + swoff(a_row, (s4 << 1) + a_csel));
                uint32_t vh[4][4], vl[4][4];
#pragma unroll
                for (int nb = 0; nb < 4; nb++) {
                    uint32_t offv = cur * 16384 + warp_n * 8192 +
                        swoff(pb_row + nb * 16, (s4 << 1) + b_csel);
                    ldsm4(vh[nb], sbm + ATT_VHI + offv);
                    ldsm4(vl[nb], sbm + ATT_VLO + offv);
                }
#pragma unroll
                for (int nj = 0; nj < 8; nj++) {
                    const uint32_t* ph = &vh[nj >> 1][(nj & 1) * 2];
                    const uint32_t* pl = &vl[nj >> 1][(nj & 1) * 2];
                    mma16816(o[nj], ap, ph);
                    mma16816(o[nj], ap, pl);
                }
            }
        }
    }

    float inv0 = 1.0f / lrow[warp_m * 16 + qrow];
    float inv1 = 1.0f / lrow[warp_m * 16 + qrow + 8];
#pragma unroll
    for (int nj = 0; nj < 8; nj++) {
        int m = q_start + warp_m * 16 + qrow;
        int col = h * HD + warp_n * 64 + nj * 8 + qcol;
        *(__half2*)(oh + (size_t)m * DM + col) =
            __floats2half2_rn(o[nj][0] * inv0, o[nj][1] * inv0);
        *(__half2*)(oh + (size_t)(m + 8) * DM + col) =
            __floats2half2_rn(o[nj][2] * inv1, o[nj][3] * inv1);
    }
}

// ============================================================================
// launch
// ============================================================================
extern "C" void kernel_launch(void* const* d_in, const int* in_sizes, int n_in,
                              void* d_out, int out_size)
{
    const float* hs    = (const float*)d_in[0];
    const float* w_qkv = (const float*)d_in[1];
    const float* w_o   = (const float*)d_in[2];
    const float* cs    = (const float*)d_in[3];
    const float* sn    = (const float*)d_in[4];
    (void)in_sizes; (void)n_in;

    __half *ah, *bhi, *blo, *bohi, *bolo, *qhi, *qlo, *khi, *klo, *vthi, *vtlo;
    cudaGetSymbolAddress((void**)&ah, g_ah);
    cudaGetSymbolAddress((void**)&bhi, g_bhi);
    cudaGetSymbolAddress((void**)&blo, g_blo);
    cudaGetSymbolAddress((void**)&bohi, g_bohi);
    cudaGetSymbolAddress((void**)&bolo, g_bolo);
    cudaGetSymbolAddress((void**)&qhi, g_qhi);
    cudaGetSymbolAddress((void**)&qlo, g_qlo);
    cudaGetSymbolAddress((void**)&khi, g_khi);
    cudaGetSymbolAddress((void**)&klo, g_klo);
    cudaGetSymbolAddress((void**)&vthi, g_vthi);
    cudaGetSymbolAddress((void**)&vtlo, g_vtlo);

    static cudaStream_t s1 = nullptr, s2 = nullptr;
    static cudaEvent_t eFork = nullptr, eWqkv = nullptr, eWo = nullptr;
    static int init_done = 0;
    if (!init_done) {
        cudaFuncSetAttribute(attn_kernel, cudaFuncAttributeMaxDynamicSharedMemorySize,
                             ATT_SMEM);
        cudaFuncSetAttribute(gemm_tc_kernel<0>,
                             cudaFuncAttributeMaxDynamicSharedMemorySize, GEMM_SMEM);
        cudaFuncSetAttribute(gemm_tc_kernel<1>,
                             cudaFuncAttributeMaxDynamicSharedMemorySize, GEMM_SMEM);
        cudaStreamCreateWithFlags(&s1, cudaStreamNonBlocking);
        cudaStreamCreateWithFlags(&s2, cudaStreamNonBlocking);
        cudaEventCreateWithFlags(&eFork, cudaEventDisableTiming);
        cudaEventCreateWithFlags(&eWqkv, cudaEventDisableTiming);
        cudaEventCreateWithFlags(&eWo, cudaEventDisableTiming);
        init_done = 1;
    }

    cudaEventRecord(eFork, 0);
    cudaStreamWaitEvent(s1, eFork, 0);
    cudaStreamWaitEvent(s2, eFork, 0);

    split_kernel<<<(QKV_N * DM / 8) / 256, 256, 0, s1>>>(
        w_qkv, bhi, blo, QKV_N * DM / 8);
    cudaEventRecord(eWqkv, s1);

    split_kernel<<<(DM * DM / 8) / 256, 256, 0, s2>>>(
        w_o, bohi, bolo, DM * DM / 8);
    cudaEventRecord(eWo, s2);

    cvt_half_kernel<<<(T_TOK * DM / 8) / 256, 256>>>(hs, ah, T_TOK * DM / 8);
    cudaStreamWaitEvent(0, eWqkv, 0);

    // QKV projection with fused clip+RoPE+split / V-transpose epilogue
    gemm_tc_kernel<1><<<dim3(QKV_N / 128, T_TOK / 128), 256, GEMM_SMEM>>>(
        ah, bhi, blo, nullptr, QKV_N, cs, sn,
        qhi, qlo, khi, klo, vthi, vtlo);

    // tensor-core flash attention -> fp16 O into g_ah
    attn_kernel<<<dim3(32, NH), 256, ATT_SMEM>>>(qhi, qlo, khi, klo, vthi, vtlo, ah);

    // output projection
    cudaStreamWaitEvent(0, eWo, 0);
    gemm_tc_kernel<0><<<dim3(DM / 128, T_TOK / 128), 256, GEMM_SMEM>>>(
        ah, bohi, bolo, (float*)d_out, DM, nullptr, nullptr,
        nullptr, nullptr, nullptr, nullptr, nullptr, nullptr);
}